// round 1
// baseline (speedup 1.0000x reference)
#include <cuda_runtime.h>
#include <cuda_bf16.h>
#include <math.h>

#define NN 1024
#define THREADS 256

// (1-p)*a + p*b, componentwise on float2
__device__ __forceinline__ float2 lerp2(float2 a, float2 b, float p) {
    return make_float2(fmaf(p, b.x - a.x, a.x), fmaf(p, b.y - a.y, a.y));
}

__global__ __launch_bounds__(THREADS) void butterfly_kernel(
    const float* __restrict__ x,
    const float* __restrict__ perm_logit,
    const float* __restrict__ abcd,
    const float* __restrict__ bvec,
    float* __restrict__ out)
{
    __shared__ float2 buf0[NN];
    __shared__ float2 buf1[NN];

    const int tid = threadIdx.x;
    const long row = blockIdx.x;

    // Load row: h = x + 0i  (coalesced global, conflict-free shared)
    const float* xr = x + row * NN;
#pragma unroll
    for (int k = 0; k < 4; ++k) {
        int t = tid + THREADS * k;
        buf0[t] = make_float2(xr[t], 0.0f);
    }
    __syncthreads();

    float2* cur = buf0;
    float2* nxt = buf1;

    for (int d = 0; d < 2; ++d) {
        const float p0 = 1.0f / (1.0f + expf(-perm_logit[d * 3 + 0]));
        const float p1 = 1.0f / (1.0f + expf(-perm_logit[d * 3 + 1]));
        const float p2 = 1.0f / (1.0f + expf(-perm_logit[d * 3 + 2]));

        // ---- Perm factors, m = 4, 8, ..., 1024 (reversed(perm_sizes)) ----
        // One fused pass per factor: output at position p and its mirror
        // (within the same half) are computed together; both are lerps of
        // g(p), g(mirror) where g = eo-mix of the input.
#pragma unroll
        for (int s = 0; s < 9; ++s) {
            const int half  = 2 << s;   // m/2
            const int quart = 1 << s;   // m/4
#pragma unroll
            for (int qq = 0; qq < 2; ++qq) {
                const int q   = tid + qq * THREADS;      // pair slot in [0,512)
                const int blk = q >> (s + 1);            // q / (m/2)
                const int w   = q & (half - 1);
                const int hh  = w >> s;                  // which half (0/1)
                const int j   = w & (quart - 1);
                const int base = blk << (s + 2);         // blk * m
                const int pa = hh * half + j;                 // position
                const int pb = hh * half + (half - 1 - j);    // its mirror
                // even/odd-separation source index within block of m
                const int ea = (pa < half) ? (2 * pa) : (2 * (pa - half) + 1);
                const int eb = (pb < half) ? (2 * pb) : (2 * (pb - half) + 1);
                float2 ha  = cur[base + pa];
                float2 hea = cur[base + ea];
                float2 hb  = cur[base + pb];
                float2 heb = cur[base + eb];
                float2 ga = lerp2(ha, hea, p0);
                float2 gb = lerp2(hb, heb, p0);
                const float pm = hh ? p2 : p1;
                nxt[base + pa] = lerp2(ga, gb, pm);
                nxt[base + pb] = lerp2(gb, ga, pm);
            }
            __syncthreads();
            float2* tmp = cur; cur = nxt; nxt = tmp;
        }

        // ---- Diag factors, m = 2, 4, ..., 1024 (reversed(offs)) ----
        // ABCD offsets into abcd[d, :, :] for m = 2<<s:
        const int doffs[10] = {4088, 4080, 4064, 4032, 3968, 3840, 3584, 3072, 2048, 0};
#pragma unroll
        for (int s = 0; s < 10; ++s) {
            const int half = 1 << s;  // m/2
            const float2* A = (const float2*)(abcd + (size_t)(d * 4092 + doffs[s]) * 2);
#pragma unroll
            for (int qq = 0; qq < 2; ++qq) {
                const int q   = tid + qq * THREADS;   // pair slot in [0,512)
                const int blk = q >> s;
                const int k   = q & (half - 1);
                const int t0  = (blk << (s + 1)) + k;
                const int t1  = t0 + half;
                float2 x0 = cur[t0];
                float2 x1 = cur[t1];
                // A[i][j][k] complex at (i*2+j)*half + k
                float2 A00 = __ldg(&A[0 * half + k]);
                float2 A01 = __ldg(&A[1 * half + k]);
                float2 A10 = __ldg(&A[2 * half + k]);
                float2 A11 = __ldg(&A[3 * half + k]);
                float2 y0, y1;
                y0.x = fmaf(A00.x, x0.x, fmaf(-A00.y, x0.y, fmaf(A01.x, x1.x, -A01.y * x1.y)));
                y0.y = fmaf(A00.x, x0.y, fmaf( A00.y, x0.x, fmaf(A01.x, x1.y,  A01.y * x1.x)));
                y1.x = fmaf(A10.x, x0.x, fmaf(-A10.y, x0.y, fmaf(A11.x, x1.x, -A11.y * x1.y)));
                y1.y = fmaf(A10.x, x0.y, fmaf( A10.y, x0.x, fmaf(A11.x, x1.y,  A11.y * x1.x)));
                nxt[t0] = y0;
                nxt[t1] = y1;
            }
            __syncthreads();
            float2* tmp = cur; cur = nxt; nxt = tmp;
        }
    }

    // out = b + Re(h)
#pragma unroll
    for (int k = 0; k < 4; ++k) {
        int t = tid + THREADS * k;
        out[row * NN + t] = bvec[t] + cur[t].x;
    }
}

extern "C" void kernel_launch(void* const* d_in, const int* in_sizes, int n_in,
                              void* d_out, int out_size) {
    const float* x          = (const float*)d_in[0];
    const float* perm_logit = (const float*)d_in[1];
    const float* abcd       = (const float*)d_in[2];
    const float* bvec       = (const float*)d_in[3];
    float* out = (float*)d_out;
    const int B = in_sizes[0] / NN;   // 16384 rows
    butterfly_kernel<<<B, THREADS>>>(x, perm_logit, abcd, bvec, out);
}